// round 16
// baseline (speedup 1.0000x reference)
#include <cuda_runtime.h>
#include <cuda_fp16.h>
#include <math.h>
#include <stdint.h>

#define BB 2
#define SS 1024
#define HID 4096
#define NH 32
#define NKV 8
#define HD 128
#define LCK 3
#define MROWS (BB*SS)   // 2048
#define QDIM (NH*HD)    // 4096
#define KVDIM (NKV*HD)  // 1024
#define LOG2T 13.287712379549449f

// ---------------- scratch (static device globals; no allocations) ----------
__device__ float  g_q[(size_t)MROWS * QDIM];
__device__ float  g_k[(size_t)MROWS * KVDIM];
__device__ float  g_v[(size_t)MROWS * KVDIM];
__device__ __half g_xh[(size_t)MROWS * HID];
__device__ __half g_ah[(size_t)MROWS * QDIM];
__device__ __half g_wqh[(size_t)HID * QDIM];   // fp16 weights [K][N] (perm cols)
__device__ __half g_wkh[(size_t)HID * KVDIM];  // perm cols
__device__ __half g_wvh[(size_t)HID * KVDIM];
__device__ __half g_woh[(size_t)QDIM * HID];

// ---------------- PTX helpers -----------------------------------------------
__device__ __forceinline__ void cp16(uint32_t dst, const void* src) {
    asm volatile("cp.async.cg.shared.global [%0], [%1], 16;" :: "r"(dst), "l"(src));
}
__device__ __forceinline__ uint32_t h2u(__half2 h) {
    union { __half2 h; uint32_t u; } cv;
    cv.h = h;
    return cv.u;
}
__device__ __forceinline__ void mma16(float* c, const uint32_t* a, const uint32_t* b) {
    asm volatile(
        "mma.sync.aligned.m16n8k16.row.col.f32.f16.f16.f32 "
        "{%0,%1,%2,%3},{%4,%5,%6,%7},{%8,%9},{%0,%1,%2,%3};"
        : "+f"(c[0]), "+f"(c[1]), "+f"(c[2]), "+f"(c[3])
        : "r"(a[0]), "r"(a[1]), "r"(a[2]), "r"(a[3]), "r"(b[0]), "r"(b[1]));
}
__device__ __forceinline__ void ldsm4(uint32_t* r, uint32_t addr) {
    asm volatile(
        "ldmatrix.sync.aligned.m8n8.x4.shared.b16 {%0,%1,%2,%3}, [%4];"
        : "=r"(r[0]), "=r"(r[1]), "=r"(r[2]), "=r"(r[3]) : "r"(addr));
}
__device__ __forceinline__ void ldsm4t(uint32_t* r, uint32_t addr) {
    asm volatile(
        "ldmatrix.sync.aligned.m8n8.x4.trans.shared.b16 {%0,%1,%2,%3}, [%4];"
        : "=r"(r[0]), "=r"(r[1]), "=r"(r[2]), "=r"(r[3]) : "r"(addr));
}
// packed f32x2
__device__ __forceinline__ unsigned long long fma2(unsigned long long a,
                                                   unsigned long long b,
                                                   unsigned long long c) {
    unsigned long long d;
    asm("fma.rn.f32x2 %0, %1, %2, %3;" : "=l"(d) : "l"(a), "l"(b), "l"(c));
    return d;
}
__device__ __forceinline__ unsigned long long mul2(unsigned long long a,
                                                   unsigned long long b) {
    unsigned long long d;
    asm("mul.rn.f32x2 %0, %1, %2;" : "=l"(d) : "l"(a), "l"(b));
    return d;
}
__device__ __forceinline__ unsigned long long pack2(float x) {
    unsigned long long d;
    asm("mov.b64 %0, {%1, %2};" : "=l"(d) : "f"(x), "f"(x));
    return d;
}
__device__ __forceinline__ void unpack2(unsigned long long v, float& lo, float& hi) {
    asm("mov.b64 {%0, %1}, %2;" : "=f"(lo), "=f"(hi) : "l"(v));
}

// ---------------- fused prep: x->fp16 + convert all 4 weights ----------------
#define P_X  ((size_t)MROWS * HID / 4)
#define P_WQ ((size_t)HID * QDIM / 8)
#define P_WK ((size_t)HID * KVDIM / 8)
#define P_WV ((size_t)HID * KVDIM / 8)
#define P_WO ((size_t)QDIM * HID / 8)
#define P_TOTAL (P_X + P_WQ + P_WK + P_WV + P_WO)

__device__ __forceinline__ void cvt_plain8(const float* __restrict__ W,
                                           __half* __restrict__ P, int N, size_t i) {
    const int npw = N >> 3;
    const int k = (int)(i / npw);
    const int c8 = (int)(i - (size_t)k * npw) * 8;
    const float4 r0 = *(const float4*)(W + (size_t)k * N + c8);
    const float4 r1 = *(const float4*)(W + (size_t)k * N + c8 + 4);
    uint4 o;
    o.x = h2u(__floats2half2_rn(r0.x, r0.y));
    o.y = h2u(__floats2half2_rn(r0.z, r0.w));
    o.z = h2u(__floats2half2_rn(r1.x, r1.y));
    o.w = h2u(__floats2half2_rn(r1.z, r1.w));
    *(uint4*)(P + (size_t)k * N + c8) = o;
}

__device__ __forceinline__ void cvt_perm8(const float* __restrict__ W,
                                          __half* __restrict__ P, int N, size_t i) {
    const int npw = N >> 3;
    const int k = (int)(i / npw);
    const int c8 = (int)(i - (size_t)k * npw) * 8;
    const float* wr = W + (size_t)k * N;
    __half hv[8];
#pragma unroll
    for (int j = 0; j < 8; j++) {
        const int c = c8 + j;
        const int h = c >> 7;
        const int w = c & 127;
        const int oc = (h << 7) + (w >> 1) + ((w & 1) << 6);
        hv[j] = __float2half_rn(wr[oc]);
    }
    *(uint4*)(P + (size_t)k * N + c8) = *(uint4*)hv;
}

__global__ void prep_kernel(const float4* __restrict__ x,  __half* __restrict__ xh,
                            const float* __restrict__ Wq, __half* __restrict__ wqh,
                            const float* __restrict__ Wk, __half* __restrict__ wkh,
                            const float* __restrict__ Wv, __half* __restrict__ wvh,
                            const float* __restrict__ Wo, __half* __restrict__ woh) {
    size_t i = (size_t)blockIdx.x * 256 + threadIdx.x;
    if (i < P_X) {
        float4 v = x[i];
        *(__half2*)(xh + i * 4)     = __floats2half2_rn(v.x, v.y);
        *(__half2*)(xh + i * 4 + 2) = __floats2half2_rn(v.z, v.w);
    } else if ((i -= P_X) < P_WQ) {
        cvt_perm8(Wq, wqh, QDIM, i);
    } else if ((i -= P_WQ) < P_WK) {
        cvt_perm8(Wk, wkh, KVDIM, i);
    } else if ((i -= P_WK) < P_WV) {
        cvt_plain8(Wv, wvh, KVDIM, i);
    } else {
        i -= P_WV;
        cvt_plain8(Wo, woh, HID, i);
    }
}

// ---------------- fp16 tensor-core GEMM (merged QKV or single) ---------------
// A fp16 [M][K]; B fp16 [K][N]. B frags via ldmatrix.x4.trans.
// merged=1: bx<32 -> Q (rope), 32..39 -> K (rope), 40..47 -> V.
// merged=0: single matrix (Bq/Cq, N=Nq), no rope.
#define APITCHW 36
#define BPITCHW 68
#define ASZW (128 * APITCHW)
#define BSZW (32 * BPITCHW)
#define STGW (ASZW + BSZW)
#define GEMM_SMEM (3 * STGW * 4)  // 81408 B

__global__ __launch_bounds__(256, 2) void gemm_h(const __half* __restrict__ A,
                                                 const __half* __restrict__ Bq,
                                                 const __half* __restrict__ Bk,
                                                 const __half* __restrict__ Bv,
                                                 float* __restrict__ Cq,
                                                 float* __restrict__ Ck,
                                                 float* __restrict__ Cv,
                                                 int M, int Nq, int Nkv, int K,
                                                 int merged) {
    const int bx = blockIdx.x;
    const __half* B;
    float* C;
    int N, bn0;
    bool do_rope;
    if (merged) {
        if (bx < 32)      { B = Bq; C = Cq; N = Nq;  bn0 = bx * 128;        do_rope = true;  }
        else if (bx < 40) { B = Bk; C = Ck; N = Nkv; bn0 = (bx - 32) * 128; do_rope = true;  }
        else              { B = Bv; C = Cv; N = Nkv; bn0 = (bx - 40) * 128; do_rope = false; }
    } else {
        B = Bq; C = Cq; N = Nq; bn0 = bx * 128; do_rope = false;
    }

    extern __shared__ float sm[];
    const uint32_t smb = (uint32_t)__cvta_generic_to_shared(sm);

    const int tid  = threadIdx.x;
    const int lane = tid & 31;
    const int wid  = tid >> 5;
    const int gid  = lane >> 2;
    const int tig  = lane & 3;
    const int wm   = (wid & 1) * 64;
    const int wn   = (wid >> 1) * 32;

    const int lrow = lane & 7;
    const int lid4 = lane >> 3;
    const int a_moff = (lid4 & 1) * 8;
    const int a_woff = (lid4 >> 1) * 4;
    const int b_roff = (lid4 & 1) * 8 + lrow;
    const int b_coff = (lid4 >> 1) * 8;

    const int bm0 = blockIdx.y * 128;

    float acc[4][4][4];
#pragma unroll
    for (int mt = 0; mt < 4; mt++)
#pragma unroll
        for (int nt = 0; nt < 4; nt++)
#pragma unroll
            for (int i = 0; i < 4; i++) acc[mt][nt][i] = 0.f;

    const int T = K / 32;

    auto issue = [&](int t) {
        const uint32_t sb = smb + (uint32_t)((t % 3) * STGW * 4);
#pragma unroll
        for (int i = 0; i < 2; i++) {
            const int c = tid + i * 256;
            const int row = c >> 2;
            const int q = c & 3;
            cp16(sb + (uint32_t)(row * APITCHW * 4 + q * 16),
                 A + (size_t)(bm0 + row) * K + t * 32 + q * 8);
        }
#pragma unroll
        for (int i = 0; i < 2; i++) {
            const int c = tid + i * 256;
            const int kk = c >> 4;
            const int h8 = (c & 15) * 8;
            cp16(sb + (uint32_t)((ASZW + kk * BPITCHW) * 4 + h8 * 2),
                 B + (size_t)(t * 32 + kk) * N + bn0 + h8);
        }
        asm volatile("cp.async.commit_group;");
    };

    issue(0);
    issue(1);

    for (int t = 0; t < T; t++) {
        if (t < T - 1) { asm volatile("cp.async.wait_group 1;"); }
        else           { asm volatile("cp.async.wait_group 0;"); }
        __syncthreads();
        if (t + 2 < T) issue(t + 2);

        const int so = (t % 3) * STGW;
#pragma unroll
        for (int ks = 0; ks < 2; ks++) {
            const int w0 = ks * 8;
            uint32_t af[4][4];
#pragma unroll
            for (int mt = 0; mt < 4; mt++) {
                const uint32_t addr = smb + (uint32_t)(
                    (so + (wm + mt * 16 + a_moff + lrow) * APITCHW + w0 + a_woff) * 4);
                ldsm4(af[mt], addr);
            }
            uint32_t bf[4][2];
#pragma unroll
            for (int pr = 0; pr < 2; pr++) {
                uint32_t bt[4];
                const int row = ks * 16 + b_roff;
                const int col = wn + pr * 16 + b_coff;
                const uint32_t addr = smb + (uint32_t)(
                    (so + ASZW + row * BPITCHW) * 4 + col * 2);
                ldsm4t(bt, addr);
                bf[pr * 2][0]     = bt[0];
                bf[pr * 2][1]     = bt[1];
                bf[pr * 2 + 1][0] = bt[2];
                bf[pr * 2 + 1][1] = bt[3];
            }
#pragma unroll
            for (int mt = 0; mt < 4; mt++)
#pragma unroll
                for (int nt = 0; nt < 4; nt++)
                    mma16(acc[mt][nt], af[mt], bf[nt]);
        }
    }

    if (!do_rope) {
#pragma unroll
        for (int mt = 0; mt < 4; mt++) {
#pragma unroll
            for (int nt = 0; nt < 4; nt++) {
                const int r = bm0 + wm + mt * 16 + gid;
                const int cc = bn0 + wn + nt * 8 + tig * 2;
                *(float2*)&C[(size_t)r * N + cc] =
                    make_float2(acc[mt][nt][0], acc[mt][nt][1]);
                *(float2*)&C[(size_t)(r + 8) * N + cc] =
                    make_float2(acc[mt][nt][2], acc[mt][nt][3]);
            }
        }
    } else {
#pragma unroll
        for (int nt = 0; nt < 4; nt++) {
            const int cc = bn0 + wn + nt * 8 + tig * 2;
            const int h = cc >> 7;
            const int u = (cc & 127) >> 1;
            const float inv = exp2f(-(float)(2 * u) * (1.0f / 128.0f) * LOG2T);
            const int c0 = h * 128 + u;
#pragma unroll
            for (int mt = 0; mt < 4; mt++) {
                const int r = bm0 + wm + mt * 16 + gid;
                {
                    const float ang = (float)(r & (SS - 1)) * inv;
                    const float cs = cosf(ang), sn = sinf(ang);
                    const float a0 = acc[mt][nt][0], a1 = acc[mt][nt][1];
                    C[(size_t)r * N + c0]      = a0 * cs - a1 * sn;
                    C[(size_t)r * N + c0 + 64] = a1 * cs + a0 * sn;
                }
                {
                    const int r2 = r + 8;
                    const float ang = (float)(r2 & (SS - 1)) * inv;
                    const float cs = cosf(ang), sn = sinf(ang);
                    const float a0 = acc[mt][nt][2], a1 = acc[mt][nt][3];
                    C[(size_t)r2 * N + c0]      = a0 * cs - a1 * sn;
                    C[(size_t)r2 * N + c0 + 64] = a1 * cs + a0 * sn;
                }
            }
        }
    }
}

// ---------------- flash attention v7: 4 q/thread + skip-rescale --------------
#define ATT_STGF (2 * 32 * 128)
#define ATT_SMEM (3 * ATT_STGF * 4)  // 98304 B

__global__ __launch_bounds__(256, 2) void attn_kernel(
        const float* __restrict__ q,
        const float* __restrict__ k,
        const float* __restrict__ v,
        const float* __restrict__ ksuf,
        const float* __restrict__ vsuf,
        const int* __restrict__ validp,
        __half* __restrict__ outh) {
    extern __shared__ float smA[];
    const uint32_t smb = (uint32_t)__cvta_generic_to_shared(smA);

    const int valid = *validp;
    const int hb = blockIdx.x;
    const int h  = hb >> 1;
    const int b  = hb & 1;
    const int bx = 15 - blockIdx.y;          // heavy-first scheduling
    const int kvh = h >> 2;
    const int tid = threadIdx.x;
    const int q0base = bx * 64;

    if (q0base >= valid) {
        const __half2 z2 = __floats2half2_rn(0.f, 0.f);
        const int row = tid >> 6;
        const int col = (tid & 63) * 2;
#pragma unroll
        for (int r = 0; r < 64; r += 4) {
            *(__half2*)(outh + (size_t)(b * SS + q0base + r + row) * QDIM + h * HD + col) = z2;
        }
        return;
    }

    const int wid  = tid >> 5;
    const int lane = tid & 31;
    const int sub  = lane & 15;
    const int qg   = lane >> 4;
    const int r    = sub & 3;
    const int q0   = q0base + wid * 8 + qg * 4;
    const int qmy  = q0 + r;

    const float scale = 0.08838834764831845f;
    const unsigned long long scale2 = pack2(scale);

    unsigned long long q2[4][4];
#pragma unroll
    for (int x = 0; x < 4; x++) {
        const float* qp = q + (size_t)(b * SS + q0 + (r ^ x)) * QDIM + h * HD;
        ulonglong2 ua = *(const ulonglong2*)(qp + sub * 4);
        ulonglong2 ub = *(const ulonglong2*)(qp + 64 + sub * 4);
        q2[x][0] = mul2(scale2, ua.x);
        q2[x][1] = mul2(scale2, ua.y);
        q2[x][2] = mul2(scale2, ub.x);
        q2[x][3] = mul2(scale2, ub.y);
    }

    unsigned long long o2[4][4];
#pragma unroll
    for (int x = 0; x < 4; x++)
#pragma unroll
        for (int c = 0; c < 4; c++) o2[x][c] = 0ull;
    float m_my = -1e30f, l_my = 0.f;

    const float* kb_base = k + (size_t)(b * SS) * KVDIM + kvh * HD;
    const float* vb_base = v + (size_t)(b * SS) * KVDIM + kvh * HD;

    const int Tcap = (valid + 31) >> 5;
    const int T = min(2 * bx + 2, Tcap);

    auto issue = [&](int t) {
        const uint32_t sb = smb + (uint32_t)((t % 3) * ATT_STGF * 4);
        const int k0 = t * 32;
#pragma unroll
        for (int i = 0; i < 4; i++) {
            const int c = tid + i * 256;
            const int kk = c >> 5;
            const int d4 = (c & 31) * 4;
            cp16(sb + (uint32_t)((kk * 128 + d4) * 4),
                 kb_base + (size_t)(k0 + kk) * KVDIM + d4);
            cp16(sb + (uint32_t)((4096 + kk * 128 + d4) * 4),
                 vb_base + (size_t)(k0 + kk) * KVDIM + d4);
        }
        asm volatile("cp.async.commit_group;");
    };

    issue(0);
    if (T > 1) issue(1);

    for (int t = 0; t < T; t++) {
        if (t + 1 < T) { asm volatile("cp.async.wait_group 1;"); }
        else           { asm volatile("cp.async.wait_group 0;"); }
        __syncthreads();
        if (t + 2 < T) issue(t + 2);

        const float* Ks = smA + (t % 3) * ATT_STGF;
        const float* Vs = Ks + 4096;
        const int k0 = t * 32;

#pragma unroll
        for (int st = 0; st < 4; st++) {
            float sc[8];
#pragma unroll
            for (int kk8 = 0; kk8 < 8; kk8++) {
                const int kk = st * 8 + kk8;
                ulonglong2 ka = *(const ulonglong2*)&Ks[kk * 128 + sub * 4];
                ulonglong2 kb = *(const ulonglong2*)&Ks[kk * 128 + 64 + sub * 4];
                float s[4];
#pragma unroll
                for (int x = 0; x < 4; x++) {
                    unsigned long long p = fma2(q2[x][0], ka.x, 0ull);
                    p = fma2(q2[x][1], ka.y, p);
                    p = fma2(q2[x][2], kb.x, p);
                    p = fma2(q2[x][3], kb.y, p);
                    float lo, hi;
                    unpack2(p, lo, hi);
                    s[x] = lo + hi;
                }
                const float t0 = s[0] + __shfl_xor_sync(0xffffffffu, s[1], 1);
                const float t2 = s[2] + __shfl_xor_sync(0xffffffffu, s[3], 1);
                float u = t0 + __shfl_xor_sync(0xffffffffu, t2, 2);
                u += __shfl_xor_sync(0xffffffffu, u, 4);
                u += __shfl_xor_sync(0xffffffffu, u, 8);
                sc[kk8] = (k0 + kk <= qmy) ? u : -1e30f;
            }
            float tmax = sc[0];
#pragma unroll
            for (int kk8 = 1; kk8 < 8; kk8++) tmax = fmaxf(tmax, sc[kk8]);
            const float mnew = fmaxf(m_my, tmax);
            // skip-rescale: when no lane's max moved, corr==1.0 exactly ->
            // skipping the multiplies is bit-identical.
            if (__any_sync(0xffffffffu, mnew > m_my)) {
                const float corr = __expf(m_my - mnew);
                l_my *= corr;
                const float cr1 = __shfl_xor_sync(0xffffffffu, corr, 1);
                const float cr2 = __shfl_xor_sync(0xffffffffu, corr, 2);
                const float cr3 = __shfl_xor_sync(0xffffffffu, corr, 3);
                const unsigned long long cp0 = pack2(corr), cp1 = pack2(cr1);
                const unsigned long long cp2 = pack2(cr2), cp3 = pack2(cr3);
#pragma unroll
                for (int c = 0; c < 4; c++) {
                    o2[0][c] = mul2(cp0, o2[0][c]);
                    o2[1][c] = mul2(cp1, o2[1][c]);
                    o2[2][c] = mul2(cp2, o2[2][c]);
                    o2[3][c] = mul2(cp3, o2[3][c]);
                }
            }
            m_my = mnew;
#pragma unroll
            for (int kk8 = 0; kk8 < 8; kk8++) {
                const float e = __expf(sc[kk8] - mnew);
                l_my += e;
                sc[kk8] = e;
            }
#pragma unroll
            for (int kk8 = 0; kk8 < 8; kk8++) {
                const int kk = st * 8 + kk8;
                ulonglong2 va = *(const ulonglong2*)&Vs[kk * 128 + sub * 4];
                ulonglong2 vb = *(const ulonglong2*)&Vs[kk * 128 + 64 + sub * 4];
                const float e0f = sc[kk8];
                const float e1f = __shfl_xor_sync(0xffffffffu, e0f, 1);
                const float e2f = __shfl_xor_sync(0xffffffffu, e0f, 2);
                const float e3f = __shfl_xor_sync(0xffffffffu, e0f, 3);
                const unsigned long long e0 = pack2(e0f), e1 = pack2(e1f);
                const unsigned long long e2 = pack2(e2f), e3 = pack2(e3f);
                o2[0][0] = fma2(e0, va.x, o2[0][0]);
                o2[0][1] = fma2(e0, va.y, o2[0][1]);
                o2[0][2] = fma2(e0, vb.x, o2[0][2]);
                o2[0][3] = fma2(e0, vb.y, o2[0][3]);
                o2[1][0] = fma2(e1, va.x, o2[1][0]);
                o2[1][1] = fma2(e1, va.y, o2[1][1]);
                o2[1][2] = fma2(e1, vb.x, o2[1][2]);
                o2[1][3] = fma2(e1, vb.y, o2[1][3]);
                o2[2][0] = fma2(e2, va.x, o2[2][0]);
                o2[2][1] = fma2(e2, va.y, o2[2][1]);
                o2[2][2] = fma2(e2, vb.x, o2[2][2]);
                o2[2][3] = fma2(e2, vb.y, o2[2][3]);
                o2[3][0] = fma2(e3, va.x, o2[3][0]);
                o2[3][1] = fma2(e3, va.y, o2[3][1]);
                o2[3][2] = fma2(e3, vb.x, o2[3][2]);
                o2[3][3] = fma2(e3, vb.y, o2[3][3]);
            }
        }
    }

    // ---- 3 suffix keys on the diagonal ----
#pragma unroll
    for (int sj = 0; sj < LCK; sj++) {
        const size_t base_off =
            ((size_t)(b * NKV + kvh) * LCK + sj) * SS;
        float s[4];
#pragma unroll
        for (int x = 0; x < 4; x++) {
            const float* kp = ksuf + (base_off + q0 + (r ^ x)) * HD;
            ulonglong2 ua = *(const ulonglong2*)(kp + sub * 4);
            ulonglong2 ub = *(const ulonglong2*)(kp + 64 + sub * 4);
            unsigned long long p = fma2(q2[x][0], ua.x, 0ull);
            p = fma2(q2[x][1], ua.y, p);
            p = fma2(q2[x][2], ub.x, p);
            p = fma2(q2[x][3], ub.y, p);
            float lo, hi;
            unpack2(p, lo, hi);
            s[x] = lo + hi;
        }
        const float t0 = s[0] + __shfl_xor_sync(0xffffffffu, s[1], 1);
        const float t2 = s[2] + __shfl_xor_sync(0xffffffffu, s[3], 1);
        float u = t0 + __shfl_xor_sync(0xffffffffu, t2, 2);
        u += __shfl_xor_sync(0xffffffffu, u, 4);
        u += __shfl_xor_sync(0xffffffffu, u, 8);

        const float mnew = fmaxf(m_my, u);
        const float corr = __expf(m_my - mnew);
        const float e = __expf(u - mnew);
        l_my = l_my * corr + e;
        m_my = mnew;
        const float cr1 = __shfl_xor_sync(0xffffffffu, corr, 1);
        const float cr2 = __shfl_xor_sync(0xffffffffu, corr, 2);
        const float cr3 = __shfl_xor_sync(0xffffffffu, corr, 3);
        const float e1f = __shfl_xor_sync(0xffffffffu, e, 1);
        const float e2f = __shfl_xor_sync(0xffffffffu, e, 2);
        const float e3f = __shfl_xor_sync(0xffffffffu, e, 3);
        const unsigned long long cp[4] = {pack2(corr), pack2(cr1), pack2(cr2), pack2(cr3)};
        const unsigned long long ep[4] = {pack2(e), pack2(e1f), pack2(e2f), pack2(e3f)};
#pragma unroll
        for (int x = 0; x < 4; x++) {
            const float* vp = vsuf + (base_off + q0 + (r ^ x)) * HD;
            ulonglong2 va = *(const ulonglong2*)(vp + sub * 4);
            ulonglong2 vb = *(const ulonglong2*)(vp + 64 + sub * 4);
            o2[x][0] = fma2(ep[x], va.x, mul2(cp[x], o2[x][0]));
            o2[x][1] = fma2(ep[x], va.y, mul2(cp[x], o2[x][1]));
            o2[x][2] = fma2(ep[x], vb.x, mul2(cp[x], o2[x][2]));
            o2[x][3] = fma2(ep[x], vb.y, mul2(cp[x], o2[x][3]));
        }
    }

    // epilogue
    const float l1 = __shfl_xor_sync(0xffffffffu, l_my, 1);
    const float l2 = __shfl_xor_sync(0xffffffffu, l_my, 2);
    const float l3 = __shfl_xor_sync(0xffffffffu, l_my, 3);
    const float lv[4] = {l_my, l1, l2, l3};
#pragma unroll
    for (int x = 0; x < 4; x++) {
        const int qx = q0 + (r ^ x);
        const float invl = (qx < valid) ? (1.0f / lv[x]) : 0.0f;
        __half* op = outh + (size_t)(b * SS + qx) * QDIM + h * HD;
        float a0, a1, a2, a3;
        unpack2(o2[x][0], a0, a1);
        unpack2(o2[x][1], a2, a3);
        uint2 w0;
        w0.x = h2u(__floats2half2_rn(a0 * invl, a1 * invl));
        w0.y = h2u(__floats2half2_rn(a2 * invl, a3 * invl));
        *(uint2*)(op + sub * 4) = w0;
        unpack2(o2[x][2], a0, a1);
        unpack2(o2[x][3], a2, a3);
        uint2 w1;
        w1.x = h2u(__floats2half2_rn(a0 * invl, a1 * invl));
        w1.y = h2u(__floats2half2_rn(a2 * invl, a3 * invl));
        *(uint2*)(op + 64 + sub * 4) = w1;
    }
}

// ---------------- launch ----------------------------------------------------
extern "C" void kernel_launch(void* const* d_in, const int* in_sizes, int n_in,
                              void* d_out, int out_size) {
    const float* x    = (const float*)d_in[0];
    const float* ksuf = (const float*)d_in[1];
    const float* vsuf = (const float*)d_in[2];
    const float* Wq   = (const float*)d_in[3];
    const float* Wk   = (const float*)d_in[4];
    const float* Wv   = (const float*)d_in[5];
    const float* Wo   = (const float*)d_in[6];
    const int* valid  = (const int*)d_in[7];
    float* out = (float*)d_out;

    float *gq, *gk, *gv;
    __half *xh, *ah, *wqh, *wkh, *wvh, *woh;
    cudaGetSymbolAddress((void**)&gq, g_q);
    cudaGetSymbolAddress((void**)&gk, g_k);
    cudaGetSymbolAddress((void**)&gv, g_v);
    cudaGetSymbolAddress((void**)&xh, g_xh);
    cudaGetSymbolAddress((void**)&ah, g_ah);
    cudaGetSymbolAddress((void**)&wqh, g_wqh);
    cudaGetSymbolAddress((void**)&wkh, g_wkh);
    cudaGetSymbolAddress((void**)&wvh, g_wvh);
    cudaGetSymbolAddress((void**)&woh, g_woh);

    cudaFuncSetAttribute(gemm_h, cudaFuncAttributeMaxDynamicSharedMemorySize, GEMM_SMEM);
    cudaFuncSetAttribute(attn_kernel, cudaFuncAttributeMaxDynamicSharedMemorySize, ATT_SMEM);

    // 0: fused prep
    prep_kernel<<<(unsigned)(P_TOTAL / 256), 256>>>(
        (const float4*)x, xh, Wq, wqh, Wk, wkh, Wv, wvh, Wo, woh);

    // 1: merged Q+K+V projections (48 N-tiles x 16 M-tiles = 768 CTAs)
    gemm_h<<<dim3(48, MROWS / 128), 256, GEMM_SMEM>>>(
        xh, wqh, wkh, wvh, gq, gk, gv, MROWS, QDIM, KVDIM, HID, 1);

    // 2: attention (heavy CTAs first)
    attn_kernel<<<dim3(NH * BB, SS / 64), 256, ATT_SMEM>>>(
        gq, gk, gv, ksuf, vsuf, valid, ah);

    // 3: output projection
    gemm_h<<<dim3(QDIM / 128, MROWS / 128), 256, GEMM_SMEM>>>(
        ah, woh, woh, woh, out, out, out, MROWS, QDIM, 0, QDIM, 0);
}

// round 17
// speedup vs baseline: 1.5606x; 1.5606x over previous
#include <cuda_runtime.h>
#include <cuda_fp16.h>
#include <math.h>
#include <stdint.h>

#define BB 2
#define SS 1024
#define HID 4096
#define NH 32
#define NKV 8
#define HD 128
#define LCK 3
#define MROWS (BB*SS)   // 2048
#define QDIM (NH*HD)    // 4096
#define KVDIM (NKV*HD)  // 1024
#define LOG2T 13.287712379549449f

// ---------------- scratch (static device globals; no allocations) ----------
__device__ float  g_q[(size_t)MROWS * QDIM];
__device__ float  g_k[(size_t)MROWS * KVDIM];
__device__ float  g_v[(size_t)MROWS * KVDIM];
__device__ __half g_xh[(size_t)MROWS * HID];
__device__ __half g_ah[(size_t)MROWS * QDIM];
__device__ __half g_wqh[(size_t)HID * QDIM];   // fp16 weights [K][N] (perm cols)
__device__ __half g_wkh[(size_t)HID * KVDIM];  // perm cols
__device__ __half g_wvh[(size_t)HID * KVDIM];
__device__ __half g_woh[(size_t)QDIM * HID];

// ---------------- PTX helpers -----------------------------------------------
__device__ __forceinline__ void cp16(uint32_t dst, const void* src) {
    asm volatile("cp.async.cg.shared.global [%0], [%1], 16;" :: "r"(dst), "l"(src));
}
__device__ __forceinline__ uint32_t h2u(__half2 h) {
    union { __half2 h; uint32_t u; } cv;
    cv.h = h;
    return cv.u;
}
__device__ __forceinline__ void mma16(float* c, const uint32_t* a, const uint32_t* b) {
    asm volatile(
        "mma.sync.aligned.m16n8k16.row.col.f32.f16.f16.f32 "
        "{%0,%1,%2,%3},{%4,%5,%6,%7},{%8,%9},{%0,%1,%2,%3};"
        : "+f"(c[0]), "+f"(c[1]), "+f"(c[2]), "+f"(c[3])
        : "r"(a[0]), "r"(a[1]), "r"(a[2]), "r"(a[3]), "r"(b[0]), "r"(b[1]));
}
__device__ __forceinline__ void ldsm4(uint32_t* r, uint32_t addr) {
    asm volatile(
        "ldmatrix.sync.aligned.m8n8.x4.shared.b16 {%0,%1,%2,%3}, [%4];"
        : "=r"(r[0]), "=r"(r[1]), "=r"(r[2]), "=r"(r[3]) : "r"(addr));
}
__device__ __forceinline__ void ldsm4t(uint32_t* r, uint32_t addr) {
    asm volatile(
        "ldmatrix.sync.aligned.m8n8.x4.trans.shared.b16 {%0,%1,%2,%3}, [%4];"
        : "=r"(r[0]), "=r"(r[1]), "=r"(r[2]), "=r"(r[3]) : "r"(addr));
}
// packed f32x2
__device__ __forceinline__ unsigned long long fma2(unsigned long long a,
                                                   unsigned long long b,
                                                   unsigned long long c) {
    unsigned long long d;
    asm("fma.rn.f32x2 %0, %1, %2, %3;" : "=l"(d) : "l"(a), "l"(b), "l"(c));
    return d;
}
__device__ __forceinline__ unsigned long long mul2(unsigned long long a,
                                                   unsigned long long b) {
    unsigned long long d;
    asm("mul.rn.f32x2 %0, %1, %2;" : "=l"(d) : "l"(a), "l"(b));
    return d;
}
__device__ __forceinline__ unsigned long long pack2(float x) {
    unsigned long long d;
    asm("mov.b64 %0, {%1, %2};" : "=l"(d) : "f"(x), "f"(x));
    return d;
}
__device__ __forceinline__ void unpack2(unsigned long long v, float& lo, float& hi) {
    asm("mov.b64 {%0, %1}, %2;" : "=f"(lo), "=f"(hi) : "l"(v));
}

// ---------------- fused prep: x->fp16 + convert all 4 weights ----------------
#define P_X  ((size_t)MROWS * HID / 4)
#define P_WQ ((size_t)HID * QDIM / 8)
#define P_WK ((size_t)HID * KVDIM / 8)
#define P_WV ((size_t)HID * KVDIM / 8)
#define P_WO ((size_t)QDIM * HID / 8)
#define P_TOTAL (P_X + P_WQ + P_WK + P_WV + P_WO)

__device__ __forceinline__ void cvt_plain8(const float* __restrict__ W,
                                           __half* __restrict__ P, int N, size_t i) {
    const int npw = N >> 3;
    const int k = (int)(i / npw);
    const int c8 = (int)(i - (size_t)k * npw) * 8;
    const float4 r0 = *(const float4*)(W + (size_t)k * N + c8);
    const float4 r1 = *(const float4*)(W + (size_t)k * N + c8 + 4);
    uint4 o;
    o.x = h2u(__floats2half2_rn(r0.x, r0.y));
    o.y = h2u(__floats2half2_rn(r0.z, r0.w));
    o.z = h2u(__floats2half2_rn(r1.x, r1.y));
    o.w = h2u(__floats2half2_rn(r1.z, r1.w));
    *(uint4*)(P + (size_t)k * N + c8) = o;
}

__device__ __forceinline__ void cvt_perm8(const float* __restrict__ W,
                                          __half* __restrict__ P, int N, size_t i) {
    const int npw = N >> 3;
    const int k = (int)(i / npw);
    const int c8 = (int)(i - (size_t)k * npw) * 8;
    const float* wr = W + (size_t)k * N;
    __half hv[8];
#pragma unroll
    for (int j = 0; j < 8; j++) {
        const int c = c8 + j;
        const int h = c >> 7;
        const int w = c & 127;
        const int oc = (h << 7) + (w >> 1) + ((w & 1) << 6);
        hv[j] = __float2half_rn(wr[oc]);
    }
    *(uint4*)(P + (size_t)k * N + c8) = *(uint4*)hv;
}

__global__ void prep_kernel(const float4* __restrict__ x,  __half* __restrict__ xh,
                            const float* __restrict__ Wq, __half* __restrict__ wqh,
                            const float* __restrict__ Wk, __half* __restrict__ wkh,
                            const float* __restrict__ Wv, __half* __restrict__ wvh,
                            const float* __restrict__ Wo, __half* __restrict__ woh) {
    size_t i = (size_t)blockIdx.x * 256 + threadIdx.x;
    if (i < P_X) {
        float4 v = x[i];
        *(__half2*)(xh + i * 4)     = __floats2half2_rn(v.x, v.y);
        *(__half2*)(xh + i * 4 + 2) = __floats2half2_rn(v.z, v.w);
    } else if ((i -= P_X) < P_WQ) {
        cvt_perm8(Wq, wqh, QDIM, i);
    } else if ((i -= P_WQ) < P_WK) {
        cvt_perm8(Wk, wkh, KVDIM, i);
    } else if ((i -= P_WK) < P_WV) {
        cvt_plain8(Wv, wvh, KVDIM, i);
    } else {
        i -= P_WV;
        cvt_plain8(Wo, woh, HID, i);
    }
}

// ---------------- fp16 tensor-core GEMM (R15 structure, unchanged) -----------
// A fp16 [M][K]; B fp16 [K][N]. B frags via ldmatrix.x4.trans.
#define APITCHW 36
#define BPITCHW 68
#define ASZW (128 * APITCHW)
#define BSZW (32 * BPITCHW)
#define STGW (ASZW + BSZW)
#define GEMM_SMEM (3 * STGW * 4)  // 81408 B

__global__ __launch_bounds__(256, 2) void gemm_h(const __half* __restrict__ A,
                                                 const __half* __restrict__ B0,
                                                 const __half* __restrict__ B1,
                                                 float* __restrict__ C0,
                                                 float* __restrict__ C1,
                                                 int M, int N, int K, int rope_mask) {
    const __half* B = blockIdx.z ? B1 : B0;
    float* C = blockIdx.z ? C1 : C0;
    const bool do_rope = (rope_mask >> blockIdx.z) & 1;

    extern __shared__ float sm[];
    const uint32_t smb = (uint32_t)__cvta_generic_to_shared(sm);

    const int tid  = threadIdx.x;
    const int lane = tid & 31;
    const int wid  = tid >> 5;
    const int gid  = lane >> 2;
    const int tig  = lane & 3;
    const int wm   = (wid & 1) * 64;
    const int wn   = (wid >> 1) * 32;

    const int lrow = lane & 7;
    const int lid4 = lane >> 3;
    const int a_moff = (lid4 & 1) * 8;
    const int a_woff = (lid4 >> 1) * 4;
    const int b_roff = (lid4 & 1) * 8 + lrow;
    const int b_coff = (lid4 >> 1) * 8;

    const int bm0 = blockIdx.y * 128;
    const int bn0 = blockIdx.x * 128;

    float acc[4][4][4];
#pragma unroll
    for (int mt = 0; mt < 4; mt++)
#pragma unroll
        for (int nt = 0; nt < 4; nt++)
#pragma unroll
            for (int i = 0; i < 4; i++) acc[mt][nt][i] = 0.f;

    const int T = K / 32;

    auto issue = [&](int t) {
        const uint32_t sb = smb + (uint32_t)((t % 3) * STGW * 4);
#pragma unroll
        for (int i = 0; i < 2; i++) {
            const int c = tid + i * 256;
            const int row = c >> 2;
            const int q = c & 3;
            cp16(sb + (uint32_t)(row * APITCHW * 4 + q * 16),
                 A + (size_t)(bm0 + row) * K + t * 32 + q * 8);
        }
#pragma unroll
        for (int i = 0; i < 2; i++) {
            const int c = tid + i * 256;
            const int kk = c >> 4;
            const int h8 = (c & 15) * 8;
            cp16(sb + (uint32_t)((ASZW + kk * BPITCHW) * 4 + h8 * 2),
                 B + (size_t)(t * 32 + kk) * N + bn0 + h8);
        }
        asm volatile("cp.async.commit_group;");
    };

    issue(0);
    issue(1);

    for (int t = 0; t < T; t++) {
        if (t < T - 1) { asm volatile("cp.async.wait_group 1;"); }
        else           { asm volatile("cp.async.wait_group 0;"); }
        __syncthreads();
        if (t + 2 < T) issue(t + 2);

        const int so = (t % 3) * STGW;
#pragma unroll
        for (int ks = 0; ks < 2; ks++) {
            const int w0 = ks * 8;
            uint32_t af[4][4];
#pragma unroll
            for (int mt = 0; mt < 4; mt++) {
                const uint32_t addr = smb + (uint32_t)(
                    (so + (wm + mt * 16 + a_moff + lrow) * APITCHW + w0 + a_woff) * 4);
                ldsm4(af[mt], addr);
            }
            uint32_t bf[4][2];
#pragma unroll
            for (int pr = 0; pr < 2; pr++) {
                uint32_t bt[4];
                const int row = ks * 16 + b_roff;
                const int col = wn + pr * 16 + b_coff;
                const uint32_t addr = smb + (uint32_t)(
                    (so + ASZW + row * BPITCHW) * 4 + col * 2);
                ldsm4t(bt, addr);
                bf[pr * 2][0]     = bt[0];
                bf[pr * 2][1]     = bt[1];
                bf[pr * 2 + 1][0] = bt[2];
                bf[pr * 2 + 1][1] = bt[3];
            }
#pragma unroll
            for (int mt = 0; mt < 4; mt++)
#pragma unroll
                for (int nt = 0; nt < 4; nt++)
                    mma16(acc[mt][nt], af[mt], bf[nt]);
        }
    }
    __syncthreads();

    if (!do_rope) {
#pragma unroll
        for (int mt = 0; mt < 4; mt++) {
#pragma unroll
            for (int nt = 0; nt < 4; nt++) {
                const int r = bm0 + wm + mt * 16 + gid;
                const int cc = bn0 + wn + nt * 8 + tig * 2;
                *(float2*)&C[(size_t)r * N + cc] =
                    make_float2(acc[mt][nt][0], acc[mt][nt][1]);
                *(float2*)&C[(size_t)(r + 8) * N + cc] =
                    make_float2(acc[mt][nt][2], acc[mt][nt][3]);
            }
        }
    } else {
#pragma unroll
        for (int nt = 0; nt < 4; nt++) {
            const int cc = bn0 + wn + nt * 8 + tig * 2;
            const int h = cc >> 7;
            const int u = (cc & 127) >> 1;
            const float inv = exp2f(-(float)(2 * u) * (1.0f / 128.0f) * LOG2T);
            const int c0 = h * 128 + u;
#pragma unroll
            for (int mt = 0; mt < 4; mt++) {
                const int r = bm0 + wm + mt * 16 + gid;
                {
                    const float ang = (float)(r & (SS - 1)) * inv;
                    const float cs = cosf(ang), sn = sinf(ang);
                    const float a0 = acc[mt][nt][0], a1 = acc[mt][nt][1];
                    C[(size_t)r * N + c0]      = a0 * cs - a1 * sn;
                    C[(size_t)r * N + c0 + 64] = a1 * cs + a0 * sn;
                }
                {
                    const int r2 = r + 8;
                    const float ang = (float)(r2 & (SS - 1)) * inv;
                    const float cs = cosf(ang), sn = sinf(ang);
                    const float a0 = acc[mt][nt][2], a1 = acc[mt][nt][3];
                    C[(size_t)r2 * N + c0]      = a0 * cs - a1 * sn;
                    C[(size_t)r2 * N + c0 + 64] = a1 * cs + a0 * sn;
                }
            }
        }
    }
}

// ---------------- flash attention: R15 v6 + skip-rescale ---------------------
#define ATT_STGF (2 * 32 * 128)
#define ATT_SMEM (3 * ATT_STGF * 4)  // 98304 B

__global__ __launch_bounds__(256, 2) void attn_kernel(
        const float* __restrict__ q,
        const float* __restrict__ k,
        const float* __restrict__ v,
        const float* __restrict__ ksuf,
        const float* __restrict__ vsuf,
        const int* __restrict__ validp,
        __half* __restrict__ outh) {
    extern __shared__ float smA[];
    const uint32_t smb = (uint32_t)__cvta_generic_to_shared(smA);

    const int valid = *validp;
    const int hb = blockIdx.x;
    const int h  = hb >> 1;
    const int b  = hb & 1;
    const int bx = 15 - blockIdx.y;          // heavy-first scheduling
    const int kvh = h >> 2;
    const int tid = threadIdx.x;
    const int q0base = bx * 64;

    if (q0base >= valid) {
        const __half2 z2 = __floats2half2_rn(0.f, 0.f);
        const int row = tid >> 6;
        const int col = (tid & 63) * 2;
#pragma unroll
        for (int r = 0; r < 64; r += 4) {
            *(__half2*)(outh + (size_t)(b * SS + q0base + r + row) * QDIM + h * HD + col) = z2;
        }
        return;
    }

    const int wid  = tid >> 5;
    const int lane = tid & 31;
    const int sub  = lane & 15;
    const int qg   = lane >> 4;
    const int r    = sub & 3;
    const int q0   = q0base + wid * 8 + qg * 4;
    const int qmy  = q0 + r;

    const float scale = 0.08838834764831845f;
    const unsigned long long scale2 = pack2(scale);

    unsigned long long q2[4][4];
#pragma unroll
    for (int x = 0; x < 4; x++) {
        const float* qp = q + (size_t)(b * SS + q0 + (r ^ x)) * QDIM + h * HD;
        ulonglong2 ua = *(const ulonglong2*)(qp + sub * 4);
        ulonglong2 ub = *(const ulonglong2*)(qp + 64 + sub * 4);
        q2[x][0] = mul2(scale2, ua.x);
        q2[x][1] = mul2(scale2, ua.y);
        q2[x][2] = mul2(scale2, ub.x);
        q2[x][3] = mul2(scale2, ub.y);
    }

    unsigned long long o2[4][4];
#pragma unroll
    for (int x = 0; x < 4; x++)
#pragma unroll
        for (int c = 0; c < 4; c++) o2[x][c] = 0ull;
    float m_my = -1e30f, l_my = 0.f;

    const float* kb_base = k + (size_t)(b * SS) * KVDIM + kvh * HD;
    const float* vb_base = v + (size_t)(b * SS) * KVDIM + kvh * HD;

    const int Tcap = (valid + 31) >> 5;
    const int T = min(2 * bx + 2, Tcap);

    auto issue = [&](int t) {
        const uint32_t sb = smb + (uint32_t)((t % 3) * ATT_STGF * 4);
        const int k0 = t * 32;
#pragma unroll
        for (int i = 0; i < 4; i++) {
            const int c = tid + i * 256;
            const int kk = c >> 5;
            const int d4 = (c & 31) * 4;
            cp16(sb + (uint32_t)((kk * 128 + d4) * 4),
                 kb_base + (size_t)(k0 + kk) * KVDIM + d4);
            cp16(sb + (uint32_t)((4096 + kk * 128 + d4) * 4),
                 vb_base + (size_t)(k0 + kk) * KVDIM + d4);
        }
        asm volatile("cp.async.commit_group;");
    };

    issue(0);
    if (T > 1) issue(1);

    for (int t = 0; t < T; t++) {
        if (t + 1 < T) { asm volatile("cp.async.wait_group 1;"); }
        else           { asm volatile("cp.async.wait_group 0;"); }
        __syncthreads();
        if (t + 2 < T) issue(t + 2);

        const float* Ks = smA + (t % 3) * ATT_STGF;
        const float* Vs = Ks + 4096;
        const int k0 = t * 32;

#pragma unroll
        for (int st = 0; st < 4; st++) {
            float sc[8];
#pragma unroll
            for (int kk8 = 0; kk8 < 8; kk8++) {
                const int kk = st * 8 + kk8;
                ulonglong2 ka = *(const ulonglong2*)&Ks[kk * 128 + sub * 4];
                ulonglong2 kb = *(const ulonglong2*)&Ks[kk * 128 + 64 + sub * 4];
                float s[4];
#pragma unroll
                for (int x = 0; x < 4; x++) {
                    unsigned long long p = fma2(q2[x][0], ka.x, 0ull);
                    p = fma2(q2[x][1], ka.y, p);
                    p = fma2(q2[x][2], kb.x, p);
                    p = fma2(q2[x][3], kb.y, p);
                    float lo, hi;
                    unpack2(p, lo, hi);
                    s[x] = lo + hi;
                }
                const float t0 = s[0] + __shfl_xor_sync(0xffffffffu, s[1], 1);
                const float t2 = s[2] + __shfl_xor_sync(0xffffffffu, s[3], 1);
                float u = t0 + __shfl_xor_sync(0xffffffffu, t2, 2);
                u += __shfl_xor_sync(0xffffffffu, u, 4);
                u += __shfl_xor_sync(0xffffffffu, u, 8);
                sc[kk8] = (k0 + kk <= qmy) ? u : -1e30f;
            }
            float tmax = sc[0];
#pragma unroll
            for (int kk8 = 1; kk8 < 8; kk8++) tmax = fmaxf(tmax, sc[kk8]);
            const float mnew = fmaxf(m_my, tmax);
            // skip-rescale: when no lane's max moved, corr==1.0 exactly ->
            // skipping the multiplies is bit-identical.
            if (__any_sync(0xffffffffu, mnew > m_my)) {
                const float corr = __expf(m_my - mnew);
                l_my *= corr;
                const float cr1 = __shfl_xor_sync(0xffffffffu, corr, 1);
                const float cr2 = __shfl_xor_sync(0xffffffffu, corr, 2);
                const float cr3 = __shfl_xor_sync(0xffffffffu, corr, 3);
                const unsigned long long cp0 = pack2(corr), cp1 = pack2(cr1);
                const unsigned long long cp2 = pack2(cr2), cp3 = pack2(cr3);
#pragma unroll
                for (int c = 0; c < 4; c++) {
                    o2[0][c] = mul2(cp0, o2[0][c]);
                    o2[1][c] = mul2(cp1, o2[1][c]);
                    o2[2][c] = mul2(cp2, o2[2][c]);
                    o2[3][c] = mul2(cp3, o2[3][c]);
                }
            }
            m_my = mnew;
#pragma unroll
            for (int kk8 = 0; kk8 < 8; kk8++) {
                const float e = __expf(sc[kk8] - mnew);
                l_my += e;
                sc[kk8] = e;
            }
#pragma unroll
            for (int kk8 = 0; kk8 < 8; kk8++) {
                const int kk = st * 8 + kk8;
                ulonglong2 va = *(const ulonglong2*)&Vs[kk * 128 + sub * 4];
                ulonglong2 vb = *(const ulonglong2*)&Vs[kk * 128 + 64 + sub * 4];
                const float e0f = sc[kk8];
                const float e1f = __shfl_xor_sync(0xffffffffu, e0f, 1);
                const float e2f = __shfl_xor_sync(0xffffffffu, e0f, 2);
                const float e3f = __shfl_xor_sync(0xffffffffu, e0f, 3);
                const unsigned long long e0 = pack2(e0f), e1 = pack2(e1f);
                const unsigned long long e2 = pack2(e2f), e3 = pack2(e3f);
                o2[0][0] = fma2(e0, va.x, o2[0][0]);
                o2[0][1] = fma2(e0, va.y, o2[0][1]);
                o2[0][2] = fma2(e0, vb.x, o2[0][2]);
                o2[0][3] = fma2(e0, vb.y, o2[0][3]);
                o2[1][0] = fma2(e1, va.x, o2[1][0]);
                o2[1][1] = fma2(e1, va.y, o2[1][1]);
                o2[1][2] = fma2(e1, vb.x, o2[1][2]);
                o2[1][3] = fma2(e1, vb.y, o2[1][3]);
                o2[2][0] = fma2(e2, va.x, o2[2][0]);
                o2[2][1] = fma2(e2, va.y, o2[2][1]);
                o2[2][2] = fma2(e2, vb.x, o2[2][2]);
                o2[2][3] = fma2(e2, vb.y, o2[2][3]);
                o2[3][0] = fma2(e3, va.x, o2[3][0]);
                o2[3][1] = fma2(e3, va.y, o2[3][1]);
                o2[3][2] = fma2(e3, vb.x, o2[3][2]);
                o2[3][3] = fma2(e3, vb.y, o2[3][3]);
            }
        }
    }

    // ---- 3 suffix keys on the diagonal ----
#pragma unroll
    for (int sj = 0; sj < LCK; sj++) {
        const size_t base_off =
            ((size_t)(b * NKV + kvh) * LCK + sj) * SS;
        float s[4];
#pragma unroll
        for (int x = 0; x < 4; x++) {
            const float* kp = ksuf + (base_off + q0 + (r ^ x)) * HD;
            ulonglong2 ua = *(const ulonglong2*)(kp + sub * 4);
            ulonglong2 ub = *(const ulonglong2*)(kp + 64 + sub * 4);
            unsigned long long p = fma2(q2[x][0], ua.x, 0ull);
            p = fma2(q2[x][1], ua.y, p);
            p = fma2(q2[x][2], ub.x, p);
            p = fma2(q2[x][3], ub.y, p);
            float lo, hi;
            unpack2(p, lo, hi);
            s[x] = lo + hi;
        }
        const float t0 = s[0] + __shfl_xor_sync(0xffffffffu, s[1], 1);
        const float t2 = s[2] + __shfl_xor_sync(0xffffffffu, s[3], 1);
        float u = t0 + __shfl_xor_sync(0xffffffffu, t2, 2);
        u += __shfl_xor_sync(0xffffffffu, u, 4);
        u += __shfl_xor_sync(0xffffffffu, u, 8);

        const float mnew = fmaxf(m_my, u);
        const float corr = __expf(m_my - mnew);
        const float e = __expf(u - mnew);
        l_my = l_my * corr + e;
        m_my = mnew;
        const float cr1 = __shfl_xor_sync(0xffffffffu, corr, 1);
        const float cr2 = __shfl_xor_sync(0xffffffffu, corr, 2);
        const float cr3 = __shfl_xor_sync(0xffffffffu, corr, 3);
        const float e1f = __shfl_xor_sync(0xffffffffu, e, 1);
        const float e2f = __shfl_xor_sync(0xffffffffu, e, 2);
        const float e3f = __shfl_xor_sync(0xffffffffu, e, 3);
        const unsigned long long cp[4] = {pack2(corr), pack2(cr1), pack2(cr2), pack2(cr3)};
        const unsigned long long ep[4] = {pack2(e), pack2(e1f), pack2(e2f), pack2(e3f)};
#pragma unroll
        for (int x = 0; x < 4; x++) {
            const float* vp = vsuf + (base_off + q0 + (r ^ x)) * HD;
            ulonglong2 va = *(const ulonglong2*)(vp + sub * 4);
            ulonglong2 vb = *(const ulonglong2*)(vp + 64 + sub * 4);
            o2[x][0] = fma2(ep[x], va.x, mul2(cp[x], o2[x][0]));
            o2[x][1] = fma2(ep[x], va.y, mul2(cp[x], o2[x][1]));
            o2[x][2] = fma2(ep[x], vb.x, mul2(cp[x], o2[x][2]));
            o2[x][3] = fma2(ep[x], vb.y, mul2(cp[x], o2[x][3]));
        }
    }

    // epilogue
    const float l1 = __shfl_xor_sync(0xffffffffu, l_my, 1);
    const float l2 = __shfl_xor_sync(0xffffffffu, l_my, 2);
    const float l3 = __shfl_xor_sync(0xffffffffu, l_my, 3);
    const float lv[4] = {l_my, l1, l2, l3};
#pragma unroll
    for (int x = 0; x < 4; x++) {
        const int qx = q0 + (r ^ x);
        const float invl = (qx < valid) ? (1.0f / lv[x]) : 0.0f;
        __half* op = outh + (size_t)(b * SS + qx) * QDIM + h * HD;
        float a0, a1, a2, a3;
        unpack2(o2[x][0], a0, a1);
        unpack2(o2[x][1], a2, a3);
        uint2 w0;
        w0.x = h2u(__floats2half2_rn(a0 * invl, a1 * invl));
        w0.y = h2u(__floats2half2_rn(a2 * invl, a3 * invl));
        *(uint2*)(op + sub * 4) = w0;
        unpack2(o2[x][2], a0, a1);
        unpack2(o2[x][3], a2, a3);
        uint2 w1;
        w1.x = h2u(__floats2half2_rn(a0 * invl, a1 * invl));
        w1.y = h2u(__floats2half2_rn(a2 * invl, a3 * invl));
        *(uint2*)(op + 64 + sub * 4) = w1;
    }
}

// ---------------- launch (R15 sequence, unchanged) ---------------------------
extern "C" void kernel_launch(void* const* d_in, const int* in_sizes, int n_in,
                              void* d_out, int out_size) {
    const float* x    = (const float*)d_in[0];
    const float* ksuf = (const float*)d_in[1];
    const float* vsuf = (const float*)d_in[2];
    const float* Wq   = (const float*)d_in[3];
    const float* Wk   = (const float*)d_in[4];
    const float* Wv   = (const float*)d_in[5];
    const float* Wo   = (const float*)d_in[6];
    const int* valid  = (const int*)d_in[7];
    float* out = (float*)d_out;

    float *gq, *gk, *gv;
    __half *xh, *ah, *wqh, *wkh, *wvh, *woh;
    cudaGetSymbolAddress((void**)&gq, g_q);
    cudaGetSymbolAddress((void**)&gk, g_k);
    cudaGetSymbolAddress((void**)&gv, g_v);
    cudaGetSymbolAddress((void**)&xh, g_xh);
    cudaGetSymbolAddress((void**)&ah, g_ah);
    cudaGetSymbolAddress((void**)&wqh, g_wqh);
    cudaGetSymbolAddress((void**)&wkh, g_wkh);
    cudaGetSymbolAddress((void**)&wvh, g_wvh);
    cudaGetSymbolAddress((void**)&woh, g_woh);

    cudaFuncSetAttribute(gemm_h, cudaFuncAttributeMaxDynamicSharedMemorySize, GEMM_SMEM);
    cudaFuncSetAttribute(attn_kernel, cudaFuncAttributeMaxDynamicSharedMemorySize, ATT_SMEM);

    // 0: fused prep
    prep_kernel<<<(unsigned)(P_TOTAL / 256), 256>>>(
        (const float4*)x, xh, Wq, wqh, Wk, wkh, Wv, wvh, Wo, woh);

    // 1: K (rope) and V projections in one launch
    gemm_h<<<dim3(KVDIM / 128, MROWS / 128, 2), 256, GEMM_SMEM>>>(
        xh, wkh, wvh, gk, gv, MROWS, KVDIM, HID, 0b01);

    // 2: Q projection (rope)
    gemm_h<<<dim3(QDIM / 128, MROWS / 128, 1), 256, GEMM_SMEM>>>(
        xh, wqh, wqh, gq, gq, MROWS, QDIM, HID, 0b01);

    // 3: attention (heavy CTAs first)
    attn_kernel<<<dim3(NH * BB, SS / 64), 256, ATT_SMEM>>>(
        gq, gk, gv, ksuf, vsuf, valid, ah);

    // 4: output projection
    gemm_h<<<dim3(QDIM / 128, MROWS / 128, 1), 256, GEMM_SMEM>>>(
        ah, woh, woh, out, out, MROWS, QDIM, QDIM, 0);
}